// round 1
// baseline (speedup 1.0000x reference)
#include <cuda_runtime.h>
#include <math.h>

// DSA_43722767073506 — algebraically collapsed form.
//
// Derivation (from the reference):
//  * log_softmax over a size-1 axis is exactly 0  =>  beta == 0  =>  ctx == 0
//    at every scan step (exact in fp32: x - x = 0, log(exp(0)) = 0).
//  * With ctx == 0 the decoder step input is din_b = d[b,t]*dec_w[0,0] + dec_b[0],
//    so h_s at step t depends only on d[:,t]; only the FINAL step (t = T-2) matters.
//  * x / encoder LSTM / all attention params never reach the output.
//  * f-gate is dead (c0 = 0). feat = [h, 0], so only d1_w[:, :H] matters, and the
//    head is linear in h:  out_b = weff . h_b + beff, with
//        weff = d2_w @ d1_w[:, :H],   beff = d2_w . d1_b + d2_b.

#define HID 128

__global__ void __launch_bounds__(HID)
dsa_collapsed_kernel(const float* __restrict__ d,      // (B, T-1)
                     const float* __restrict__ Wd,     // (4H, 1) flattened 4H
                     const float* __restrict__ bd,     // (4H,)
                     const float* __restrict__ decw,   // (1, H+1) -> only [0]
                     const float* __restrict__ decb,   // (1,)
                     const float* __restrict__ d1w,    // (H, 2H) row-major
                     const float* __restrict__ d1b,    // (H,)
                     const float* __restrict__ d2w,    // (1, H)
                     const float* __restrict__ d2b,    // (1,)
                     float* __restrict__ out,          // (B,)
                     int Bn, int Tm1)
{
    __shared__ float sweff[HID];

    const int tid  = threadIdx.x;
    const int lane = tid & 31;
    const int wrp  = tid >> 5;

    // ---- Phase 1: weff[tid] = sum_j d2w[j] * d1w[j, tid];  beff in-register ----
    float weff = 0.0f;
    float beff = 0.0f;
#pragma unroll 8
    for (int j = 0; j < HID; ++j) {
        const float a = d2w[j];
        weff = fmaf(a, d1w[j * (2 * HID) + tid], weff);
        beff = fmaf(a, d1b[j], beff);
    }
    beff += d2b[0];
    sweff[tid] = weff;
    __syncthreads();

    // ---- Preload decoder-LSTM gate weights for this lane's 4 hidden indices ----
    // Gate order i,f,g,o; the f gate is dead (f * c0 == 0).
    float wi4[4], wg4[4], wo4[4], bi4[4], bg4[4], bo4[4], sw4[4];
#pragma unroll
    for (int m = 0; m < 4; ++m) {
        const int k = lane + 32 * m;
        wi4[m] = Wd[k];
        wg4[m] = Wd[2 * HID + k];
        wo4[m] = Wd[3 * HID + k];
        bi4[m] = bd[k];
        bg4[m] = bd[2 * HID + k];
        bo4[m] = bd[3 * HID + k];
        sw4[m] = sweff[k];
    }

    const float dw0 = decw[0];
    const float db0 = decb[0];

    // ---- Phase 2: each warp handles a contiguous chunk of batches ----
    const int nb = (Bn + 3) >> 2;  // batches per warp (4 warps)
    for (int i = 0; i < nb; ++i) {
        const int b = wrp * nb + i;
        if (b >= Bn) break;

        // u = d[b, T-2] * dec_w[0,0] + dec_b[0]
        const float u = fmaf(d[b * Tm1 + (Tm1 - 1)], dw0, db0);

        float acc = 0.0f;
#pragma unroll
        for (int m = 0; m < 4; ++m) {
            const float zi = fmaf(u, wi4[m], bi4[m]);
            const float zg = fmaf(u, wg4[m], bg4[m]);
            const float zo = fmaf(u, wo4[m], bo4[m]);
            const float si = 1.0f / (1.0f + expf(-zi));
            const float so = 1.0f / (1.0f + expf(-zo));
            const float c  = si * tanhf(zg);
            const float h  = so * tanhf(c);
            acc = fmaf(sw4[m], h, acc);
        }
        // warp reduction over the 128 hidden contributions (32 lanes x 4 each)
#pragma unroll
        for (int off = 16; off; off >>= 1)
            acc += __shfl_xor_sync(0xFFFFFFFFu, acc, off);

        if (lane == 0)
            out[b] = acc + beff;
    }
}

extern "C" void kernel_launch(void* const* d_in, const int* in_sizes, int n_in,
                              void* d_out, int out_size)
{
    // metadata order: x, d, W_ih_e, b_e, W_ih_d, b_d, att_w1, att_b1, att_w2,
    //                 att_b2, att_v, att_vb, dec_w, dec_b, d1_w, d1_b, d2_w, d2_b
    const float* d    = (const float*)d_in[1];
    const float* Wd   = (const float*)d_in[4];
    const float* bd   = (const float*)d_in[5];
    const float* decw = (const float*)d_in[12];
    const float* decb = (const float*)d_in[13];
    const float* d1w  = (const float*)d_in[14];
    const float* d1b  = (const float*)d_in[15];
    const float* d2w  = (const float*)d_in[16];
    const float* d2b  = (const float*)d_in[17];

    const int Bn  = out_size;                 // 32
    const int Tm1 = in_sizes[1] / Bn;         // 99

    dsa_collapsed_kernel<<<1, HID>>>(d, Wd, bd, decw, decb,
                                     d1w, d1b, d2w, d2b,
                                     (float*)d_out, Bn, Tm1);
}

// round 2
// speedup vs baseline: 1.9483x; 1.9483x over previous
#include <cuda_runtime.h>
#include <math.h>

// DSA_43722767073506 — algebraically collapsed form, 2-kernel pipeline.
//
// Math (derived from the reference):
//  * log_softmax over a size-1 axis == 0 exactly => beta == 0 => ctx == 0
//    at every scan step. Only the FINAL decoder step (driven by d[:, T-2])
//    reaches the output; x / encoder / attention params are dead.
//  * f-gate dead (c0 = 0); feat = [h, 0] so only d1_w[:, :H] matters.
//  * Head is linear in h:  out_b = weff . h_b + beff,
//      weff = d2_w @ d1_w[:, :H]   (128x128 GEMV, the only real memory work)
//      beff = d2_w . d1_b + d2_b.
//
// Perf: round-1 kernel was LSU-issue bound (16K scalar LDGs on ONE SM at
// 1.82 cyc/LDG). Here the GEMV is split over 8 blocks with LDG.128 loads
// (512 vector loads per block), partials stored transposed in a __device__
// scratch; kernel 2 reduces partials (float4) and runs the tiny epilogue.

#define HID 128
#define NBLK 8            // phase-1 blocks; each handles 16 rows of d1w
#define ROWS_PER_BLK (HID / NBLK)

__device__ float g_partial[HID * NBLK];   // transposed: [col][blk]

// ---------------- Kernel 1: partial weff = d2w @ d1w[:, :128] ----------------
// grid = NBLK, block = 256 (8 warps). Warp w of block bl handles rows
// j = bl*16 + 2w, bl*16 + 2w + 1. Lane l covers cols [4l, 4l+4) via float4.
__global__ void __launch_bounds__(256)
dsa_weff_kernel(const float* __restrict__ d1w,   // (H, 2H) row-major
                const float* __restrict__ d2w)   // (1, H)
{
    __shared__ float sm[8 * HID];

    const int t    = threadIdx.x;
    const int lane = t & 31;
    const int w    = t >> 5;
    const int bl   = blockIdx.x;

    const int j0 = bl * ROWS_PER_BLK + w * 2;
    const float a0 = d2w[j0];
    const float a1 = d2w[j0 + 1];
    const float4 v0 = ((const float4*)(d1w + (size_t)j0       * (2 * HID)))[lane];
    const float4 v1 = ((const float4*)(d1w + (size_t)(j0 + 1) * (2 * HID)))[lane];

    sm[w * HID + 4 * lane + 0] = fmaf(a0, v0.x, a1 * v1.x);
    sm[w * HID + 4 * lane + 1] = fmaf(a0, v0.y, a1 * v1.y);
    sm[w * HID + 4 * lane + 2] = fmaf(a0, v0.z, a1 * v1.z);
    sm[w * HID + 4 * lane + 3] = fmaf(a0, v0.w, a1 * v1.w);
    __syncthreads();

    if (t < HID) {
        float s = 0.0f;
#pragma unroll
        for (int ww = 0; ww < 8; ++ww) s += sm[ww * HID + t];
        g_partial[t * NBLK + bl] = s;   // transposed for float4 reads in K2
    }
}

// ---------------- Kernel 2: reduce weff + collapsed LSTM epilogue ----------------
// 1 block, 1024 threads (32 warps): warp b computes out[b].
__global__ void __launch_bounds__(1024)
dsa_epilogue_kernel(const float* __restrict__ d,     // (B, T-1)
                    const float* __restrict__ Wd,    // (4H,)
                    const float* __restrict__ bd,    // (4H,)
                    const float* __restrict__ decw,  // (H+1,) -> [0]
                    const float* __restrict__ decb,  // (1,)
                    const float* __restrict__ d1b,   // (H,)
                    const float* __restrict__ d2w,   // (H,)
                    const float* __restrict__ d2b,   // (1,)
                    float* __restrict__ out,         // (B,)
                    int Bn, int Tm1)
{
    __shared__ float sweff[HID];
    __shared__ float sb[HID];
    __shared__ float sbeff;

    const int t    = threadIdx.x;
    const int lane = t & 31;
    const int wrp  = t >> 5;

    if (t < HID) {
        const float4* gp = (const float4*)g_partial;   // [col][8] -> 2 float4/col
        float4 p0 = gp[t * 2 + 0];
        float4 p1 = gp[t * 2 + 1];
        sweff[t] = ((p0.x + p0.y) + (p0.z + p0.w)) +
                   ((p1.x + p1.y) + (p1.z + p1.w));
        sb[t] = d2w[t] * d1b[t];
    }
    __syncthreads();
#pragma unroll
    for (int off = 64; off >= 1; off >>= 1) {
        if (t < off) sb[t] += sb[t + off];
        __syncthreads();
    }
    if (t == 0) sbeff = sb[0] + d2b[0];
    __syncthreads();

    const int b = wrp;           // one batch per warp
    if (b >= Bn) return;

    // u = d[b, T-2] * dec_w[0,0] + dec_b[0]
    const float u = fmaf(d[b * Tm1 + (Tm1 - 1)], decw[0], decb[0]);

    float acc = 0.0f;
#pragma unroll
    for (int m = 0; m < 4; ++m) {
        const int k = lane + 32 * m;
        const float zi = fmaf(u, Wd[k],           bd[k]);
        const float zg = fmaf(u, Wd[2 * HID + k], bd[2 * HID + k]);
        const float zo = fmaf(u, Wd[3 * HID + k], bd[3 * HID + k]);
        const float si = 1.0f / (1.0f + __expf(-zi));
        const float so = 1.0f / (1.0f + __expf(-zo));
        const float c  = si * tanhf(zg);
        const float h  = so * tanhf(c);
        acc = fmaf(sweff[k], h, acc);
    }
#pragma unroll
    for (int off = 16; off; off >>= 1)
        acc += __shfl_xor_sync(0xFFFFFFFFu, acc, off);

    if (lane == 0)
        out[b] = acc + sbeff;
}

extern "C" void kernel_launch(void* const* d_in, const int* in_sizes, int n_in,
                              void* d_out, int out_size)
{
    // metadata order: x, d, W_ih_e, b_e, W_ih_d, b_d, att_w1, att_b1, att_w2,
    //                 att_b2, att_v, att_vb, dec_w, dec_b, d1_w, d1_b, d2_w, d2_b
    const float* d    = (const float*)d_in[1];
    const float* Wd   = (const float*)d_in[4];
    const float* bd   = (const float*)d_in[5];
    const float* decw = (const float*)d_in[12];
    const float* decb = (const float*)d_in[13];
    const float* d1w  = (const float*)d_in[14];
    const float* d1b  = (const float*)d_in[15];
    const float* d2w  = (const float*)d_in[16];
    const float* d2b  = (const float*)d_in[17];

    const int Bn  = out_size;                 // 32
    const int Tm1 = in_sizes[1] / Bn;         // 99

    dsa_weff_kernel<<<NBLK, 256>>>(d1w, d2w);
    dsa_epilogue_kernel<<<1, 1024>>>(d, Wd, bd, decw, decb,
                                     d1b, d2w, d2b,
                                     (float*)d_out, Bn, Tm1);
}

// round 3
// speedup vs baseline: 2.5385x; 1.3029x over previous
#include <cuda_runtime.h>
#include <math.h>

// DSA_43722767073506 — algebraically collapsed, single fused kernel.
//
// Math (derived from the reference):
//  * log_softmax over a size-1 axis == 0 exactly => beta == 0 => ctx == 0 at
//    every scan step. Only the FINAL decoder step (driven by d[:, T-2])
//    reaches the output; x / encoder / attention params are dead.
//  * f-gate dead (c0 = 0); feat = [h, 0] so only d1_w[:, :H] matters.
//  * Head is linear in h:  out_b = weff . h_b + beff,
//      weff = d2_w @ d1_w[:, :H]   (128x128 GEMV, the only real memory work)
//      beff = d2_w . d1_b + d2_b.
//
// Perf regime: launch-latency bound. Round 2 showed two tiny kernels cost
// ~8.7us mostly in per-node overhead + serial barrier chains. This version is
// ONE kernel, ONE block (1024 thr), 2 block barriers total:
//   GEMV: warp w owns rows 4w..4w+3, lane owns cols 4l..4l+3 (LDG.128, MLP=4)
//   beff: warp-0 shuffle reduction (no block tree)
//   epilogue: warp b computes out[b] with fast-math transcendentals.

#define HID 128

__global__ void __launch_bounds__(1024)
dsa_fused_kernel(const float* __restrict__ d,     // (B, T-1)
                 const float* __restrict__ Wd,    // (4H,)
                 const float* __restrict__ bd,    // (4H,)
                 const float* __restrict__ decw,  // (H+1,) -> [0]
                 const float* __restrict__ decb,  // (1,)
                 const float* __restrict__ d1w,   // (H, 2H) row-major
                 const float* __restrict__ d1b,   // (H,)
                 const float* __restrict__ d2w,   // (H,)
                 const float* __restrict__ d2b,   // (1,)
                 float* __restrict__ out,         // (B,)
                 int Bn, int Tm1)
{
    __shared__ float sm[32 * HID];   // GEMV partials, [warp][col]
    __shared__ float sweff[HID];
    __shared__ float sbeff;

    const int t    = threadIdx.x;
    const int lane = t & 31;
    const int w    = t >> 5;

    // ---- issue the epilogue's scalar loads early (hide DRAM latency) ----
    const int  b   = w;  // one batch per warp (B == 32)
    float dval = 0.0f;
    if (b < Bn) dval = d[b * Tm1 + (Tm1 - 1)];
    const float dw0 = decw[0];
    const float db0 = decb[0];

    // ---- GEMV: weff[c] = sum_j d2w[j] * d1w[j][c] ----
    // warp w: rows 4w..4w+3; lane: cols 4*lane..4*lane+3 (float4)
    float4 acc = make_float4(0.f, 0.f, 0.f, 0.f);
#pragma unroll
    for (int r = 0; r < 4; ++r) {
        const int j = w * 4 + r;
        const float  a = __ldg(d2w + j);
        const float4 v = ((const float4*)(d1w + (size_t)j * (2 * HID)))[lane];
        acc.x = fmaf(a, v.x, acc.x);
        acc.y = fmaf(a, v.y, acc.y);
        acc.z = fmaf(a, v.z, acc.z);
        acc.w = fmaf(a, v.w, acc.w);
    }
    ((float4*)(sm + w * HID))[lane] = acc;
    __syncthreads();

    // ---- reduce 32 partials per column (threads 0..127) ----
    if (t < HID) {
        float s = 0.0f;
#pragma unroll
        for (int ww = 0; ww < 32; ++ww) s += sm[ww * HID + t];
        sweff[t] = s;
    }
    // ---- beff = d2w . d1b + d2b, warp 0 shuffle reduction ----
    if (w == 0) {
        float p = 0.0f;
#pragma unroll
        for (int m = 0; m < 4; ++m) {
            const int k = lane + 32 * m;
            p = fmaf(__ldg(d2w + k), __ldg(d1b + k), p);
        }
#pragma unroll
        for (int off = 16; off; off >>= 1)
            p += __shfl_xor_sync(0xFFFFFFFFu, p, off);
        if (lane == 0) sbeff = p + d2b[0];
    }
    __syncthreads();

    // ---- collapsed decoder-LSTM epilogue: warp b -> out[b] ----
    if (b >= Bn) return;

    const float u = fmaf(dval, dw0, db0);   // decoder input at final step

    float r = 0.0f;
#pragma unroll
    for (int m = 0; m < 4; ++m) {
        const int k = lane + 32 * m;
        const float zi = fmaf(u, Wd[k],           bd[k]);
        const float zg = fmaf(u, Wd[2 * HID + k], bd[2 * HID + k]);
        const float zo = fmaf(u, Wd[3 * HID + k], bd[3 * HID + k]);
        const float si = __fdividef(1.0f, 1.0f + __expf(-zi));
        const float so = __fdividef(1.0f, 1.0f + __expf(-zo));
        // tanh(x) = (e^{2x} - 1) / (e^{2x} + 1)
        const float eg = __expf(2.0f * zg);
        const float tg = __fdividef(eg - 1.0f, eg + 1.0f);
        const float c  = si * tg;
        const float ec = __expf(2.0f * c);
        const float tc = __fdividef(ec - 1.0f, ec + 1.0f);
        const float h  = so * tc;
        r = fmaf(sweff[k], h, r);
    }
#pragma unroll
    for (int off = 16; off; off >>= 1)
        r += __shfl_xor_sync(0xFFFFFFFFu, r, off);

    if (lane == 0)
        out[b] = r + sbeff;
}

extern "C" void kernel_launch(void* const* d_in, const int* in_sizes, int n_in,
                              void* d_out, int out_size)
{
    // metadata order: x, d, W_ih_e, b_e, W_ih_d, b_d, att_w1, att_b1, att_w2,
    //                 att_b2, att_v, att_vb, dec_w, dec_b, d1_w, d1_b, d2_w, d2_b
    const float* d    = (const float*)d_in[1];
    const float* Wd   = (const float*)d_in[4];
    const float* bd   = (const float*)d_in[5];
    const float* decw = (const float*)d_in[12];
    const float* decb = (const float*)d_in[13];
    const float* d1w  = (const float*)d_in[14];
    const float* d1b  = (const float*)d_in[15];
    const float* d2w  = (const float*)d_in[16];
    const float* d2b  = (const float*)d_in[17];

    const int Bn  = out_size;                 // 32
    const int Tm1 = in_sizes[1] / Bn;         // 99

    dsa_fused_kernel<<<1, 1024>>>(d, Wd, bd, decw, decb,
                                  d1w, d1b, d2w, d2b,
                                  (float*)d_out, Bn, Tm1);
}

// round 4
// speedup vs baseline: 2.5507x; 1.0048x over previous
#include <cuda_runtime.h>
#include <math.h>

// DSA_43722767073506 — algebraically collapsed, single fused kernel (v4).
//
// Math (derived from the reference):
//  * log_softmax over a size-1 axis == 0 exactly => beta == 0 => ctx == 0 at
//    every scan step. Only the FINAL decoder step (driven by d[:, T-2])
//    reaches the output; x / encoder / attention params are dead.
//  * f-gate dead (c0 = 0); feat = [h, 0] so only d1_w[:, :H] matters.
//  * out_b = weff . h_b + beff,  weff = d2_w @ d1_w[:, :H],
//    beff = d2_w . d1_b + d2_b  (folded into the per-warp reduction).
//
// Latency-chain surgery vs v3:
//  * ALL DRAM operands prefetched in one MLP wave at kernel entry
//    (epilogue scalars no longer serialized behind the GEMV + barriers).
//  * h (transcendental chain) computed BEFORE the barrier, overlapping the
//    GEMV load->STS latency.
//  * beff folded into each epilogue warp's own shuffle reduction.

#define HID 128

__global__ void __launch_bounds__(1024)
dsa_fused_kernel(const float* __restrict__ d,     // (B, T-1)
                 const float* __restrict__ Wd,    // (4H,)
                 const float* __restrict__ bd,    // (4H,)
                 const float* __restrict__ decw,  // (H+1,) -> [0]
                 const float* __restrict__ decb,  // (1,)
                 const float* __restrict__ d1w,   // (H, 2H) row-major
                 const float* __restrict__ d1b,   // (H,)
                 const float* __restrict__ d2w,   // (H,)
                 const float* __restrict__ d2b,   // (1,)
                 float* __restrict__ out,         // (B,)
                 int Bn, int Tm1)
{
    __shared__ float sm[32 * HID];   // GEMV partials, [warp][col]
    __shared__ float sweff[HID];

    const int t    = threadIdx.x;
    const int lane = t & 31;
    const int w    = t >> 5;

    // ================= prefetch wave: issue EVERY gmem load now =================
    // epilogue scalars (one batch per warp, B == 32)
    float dval = 0.0f;
    if (w < Bn) dval = d[w * Tm1 + (Tm1 - 1)];
    const float dw0  = decw[0];
    const float db0  = decb[0];
    const float d2bv = d2b[0];

    float wi[4], wg[4], wo[4], bi[4], bg[4], bo[4], a2[4], b1[4];
#pragma unroll
    for (int m = 0; m < 4; ++m) {
        const int k = lane + 32 * m;
        wi[m] = Wd[k];
        wg[m] = Wd[2 * HID + k];
        wo[m] = Wd[3 * HID + k];
        bi[m] = bd[k];
        bg[m] = bd[2 * HID + k];
        bo[m] = bd[3 * HID + k];
        a2[m] = d2w[k];
        b1[m] = d1b[k];
    }

    // GEMV operands: warp w owns rows 4w..4w+3, lane owns cols 4l..4l+3
    float  ga[4];
    float4 gv[4];
#pragma unroll
    for (int r = 0; r < 4; ++r) {
        const int j = w * 4 + r;
        ga[r] = d2w[j];
        gv[r] = ((const float4*)(d1w + (size_t)j * (2 * HID)))[lane];
    }

    // ============== compute h + beff-partials (overlaps GEMV loads) ==============
    const float u = fmaf(dval, dw0, db0);   // decoder input at final step
    float h4[4];
    float rb = 0.0f;                         // beff partial: sum_k d2w[k]*d1b[k]
#pragma unroll
    for (int m = 0; m < 4; ++m) {
        const float zi = fmaf(u, wi[m], bi[m]);
        const float zg = fmaf(u, wg[m], bg[m]);
        const float zo = fmaf(u, wo[m], bo[m]);
        const float si = __fdividef(1.0f, 1.0f + __expf(-zi));
        const float so = __fdividef(1.0f, 1.0f + __expf(-zo));
        const float eg = __expf(2.0f * zg);                    // tanh via exp2x
        const float tg = __fdividef(eg - 1.0f, eg + 1.0f);
        const float c  = si * tg;
        const float ec = __expf(2.0f * c);
        const float tc = __fdividef(ec - 1.0f, ec + 1.0f);
        h4[m] = so * tc;
        rb = fmaf(a2[m], b1[m], rb);
    }

    // ======================= GEMV partials -> shared =======================
    float4 acc;
    acc.x = ga[0] * gv[0].x; acc.y = ga[0] * gv[0].y;
    acc.z = ga[0] * gv[0].z; acc.w = ga[0] * gv[0].w;
#pragma unroll
    for (int r = 1; r < 4; ++r) {
        acc.x = fmaf(ga[r], gv[r].x, acc.x);
        acc.y = fmaf(ga[r], gv[r].y, acc.y);
        acc.z = fmaf(ga[r], gv[r].z, acc.z);
        acc.w = fmaf(ga[r], gv[r].w, acc.w);
    }
    ((float4*)(sm + w * HID))[lane] = acc;
    __syncthreads();

    // ================= reduce 32 partials per column (t < 128) =================
    if (t < HID) {
        float s = 0.0f;
#pragma unroll
        for (int ww = 0; ww < 32; ++ww) s += sm[ww * HID + t];
        sweff[t] = s;
    }
    __syncthreads();

    // ======================= final dot + output =======================
    if (w >= Bn) return;

    float r = rb;                        // carries the beff partial
#pragma unroll
    for (int m = 0; m < 4; ++m)
        r = fmaf(sweff[lane + 32 * m], h4[m], r);
#pragma unroll
    for (int off = 16; off; off >>= 1)
        r += __shfl_xor_sync(0xFFFFFFFFu, r, off);

    if (lane == 0)
        out[w] = r + d2bv;
}

extern "C" void kernel_launch(void* const* d_in, const int* in_sizes, int n_in,
                              void* d_out, int out_size)
{
    // metadata order: x, d, W_ih_e, b_e, W_ih_d, b_d, att_w1, att_b1, att_w2,
    //                 att_b2, att_v, att_vb, dec_w, dec_b, d1_w, d1_b, d2_w, d2_b
    const float* d    = (const float*)d_in[1];
    const float* Wd   = (const float*)d_in[4];
    const float* bd   = (const float*)d_in[5];
    const float* decw = (const float*)d_in[12];
    const float* decb = (const float*)d_in[13];
    const float* d1w  = (const float*)d_in[14];
    const float* d1b  = (const float*)d_in[15];
    const float* d2w  = (const float*)d_in[16];
    const float* d2b  = (const float*)d_in[17];

    const int Bn  = out_size;                 // 32
    const int Tm1 = in_sizes[1] / Bn;         // 99

    dsa_fused_kernel<<<1, 1024>>>(d, Wd, bd, decw, decb,
                                  d1w, d1b, d2w, d2b,
                                  (float*)d_out, Bn, Tm1);
}